// round 15
// baseline (speedup 1.0000x reference)
#include <cuda_runtime.h>
#include <cuda_bf16.h>
#include <math.h>
#include <stdint.h>

// ---------------------------------------------------------------------------
// TemporalWormhole: bf16 m16n8k16 mma.sync GEMMs (R9 core) + MMA flash
// attention, per-band KT in {192,128,96}, split-half K/V smem (2 CTAs/SM).
// B=8, T=1024, D=256. M = 8192 tokens/band.
// ---------------------------------------------------------------------------

#define D_DIM   256
#define M_ROWS  8192
#define SLAB    (M_ROWS * D_DIM)

__device__ float g_u[7 * SLAB];

__device__ __nv_bfloat16 g_qbf[7 * SLAB];
__device__ __nv_bfloat16 g_kbf[7 * SLAB];
__device__ __nv_bfloat16 g_vbf[7 * SLAB];
__device__ __nv_bfloat16 g_band_bf[7 * SLAB];
__device__ __nv_bfloat16 g_ctx_bf[7 * SLAB];
__device__ __nv_bfloat16 g_u_bf[7 * SLAB];
__device__ __nv_bfloat16 g_other_bf[SLAB];

#define OFF_QW  0
#define OFF_KW  458752
#define OFF_VW  917504
#define OFF_CW  1376256
#define OFF_CRW 1572864
#define OFF_BW  1769472
#define OFF_GW  1835008
__device__ __nv_bfloat16 g_wbf[2752512];

__constant__ int c_win[7] = {128, 64, 32, 16, 16, 8, 4};

struct BandPtrs { const float* p[7]; };
struct WSrc     { const float* p[7]; };

// ---------------------------- PTX helpers -----------------------------------
__device__ __forceinline__ uint32_t smem_u32(const void* p) {
    uint32_t a;
    asm("{ .reg .u64 t; cvta.to.shared.u64 t, %1; cvt.u32.u64 %0, t; }"
        : "=r"(a) : "l"(p));
    return a;
}

__device__ __forceinline__ void cp16(uint32_t dst, const void* src) {
    asm volatile("cp.async.cg.shared.global [%0], [%1], 16;"
                 :: "r"(dst), "l"(src) : "memory");
}
#define CP_COMMIT() asm volatile("cp.async.commit_group;" ::: "memory")
template<int N>
__device__ __forceinline__ void cp_wait() {
    asm volatile("cp.async.wait_group %0;" :: "n"(N) : "memory");
}

__device__ __forceinline__ void ldsm_x4(uint32_t addr, uint32_t r[4]) {
    asm volatile("ldmatrix.sync.aligned.m8n8.x4.shared.b16 {%0,%1,%2,%3}, [%4];"
        : "=r"(r[0]), "=r"(r[1]), "=r"(r[2]), "=r"(r[3]) : "r"(addr));
}

__device__ __forceinline__ void mma_bf16(float4& d, const uint32_t a[4],
                                         uint32_t b0, uint32_t b1) {
    asm volatile(
        "mma.sync.aligned.m16n8k16.row.col.f32.bf16.bf16.f32 "
        "{%0,%1,%2,%3}, {%4,%5,%6,%7}, {%8,%9}, {%0,%1,%2,%3};"
        : "+f"(d.x), "+f"(d.y), "+f"(d.z), "+f"(d.w)
        : "r"(a[0]), "r"(a[1]), "r"(a[2]), "r"(a[3]), "r"(b0), "r"(b1));
}

// ---------------------------------------------------------------------------
// bf16 GEMM (exact R9 core).
// ---------------------------------------------------------------------------

#define STAGES 4
#define ROWB   80

template<bool GATE>
__device__ __forceinline__ void issue_chunk(
    int kn, int tid, uint32_t sA, uint32_t sB,
    const __nv_bfloat16* __restrict__ A0, const __nv_bfloat16* __restrict__ A1,
    const __nv_bfloat16* __restrict__ W, int ldw, int row0, int col0)
{
    const __nv_bfloat16* Ab; int k0;
    if (GATE && kn >= 8) { Ab = A1; k0 = (kn - 8) * 32; }
    else                 { Ab = A0; k0 = kn * 32; }
    const int kw0 = kn * 32;
    const int s   = kn & (STAGES - 1);
#pragma unroll
    for (int i = 0; i < 2; i++) {
        int idx = tid + i * 256;
        int r = idx >> 2, q = idx & 3;
        uint32_t off = (uint32_t)((s * 128 + r) * ROWB + q * 16);
        cp16(sA + off, Ab + (size_t)(row0 + r) * 256 + k0 + q * 8);
        cp16(sB + off, W + (size_t)(col0 + r) * ldw + kw0 + q * 8);
    }
    CP_COMMIT();
}

template<int MODE>
__device__ __forceinline__ void gemm_body(
    const __nv_bfloat16* __restrict__ A0,
    const __nv_bfloat16* __restrict__ A1,
    const __nv_bfloat16* __restrict__ W, int ldw,
    const float* __restrict__ bias,
    float* __restrict__ C,
    __nv_bfloat16* __restrict__ Cbf,
    const float* __restrict__ Xf,
    const float* __restrict__ Uf)
{
    const bool GATE = (MODE == 2);
    const int NKT = GATE ? 16 : 8;
    __shared__ __align__(16) __nv_bfloat16 smA[STAGES * 128 * 40];
    __shared__ __align__(16) __nv_bfloat16 smB[STAGES * 128 * 40];

    const int tid  = threadIdx.x;
    const int wid  = tid >> 5;
    const int lane = tid & 31;
    const int g    = lane >> 2;
    const int t    = lane & 3;
    const int m0   = (wid & 1) * 64;
    const int n0   = (wid >> 1) * 32;
    const int row0 = blockIdx.x * 128;
    const int col0 = blockIdx.y * 128;
    const int lr   = lane & 15;
    const int lh   = lane >> 4;

    const uint32_t sA = smem_u32(smA);
    const uint32_t sB = smem_u32(smB);

    float4 acc[4][4];
#pragma unroll
    for (int mt = 0; mt < 4; mt++)
#pragma unroll
        for (int nt = 0; nt < 4; nt++) acc[mt][nt] = make_float4(0.f, 0.f, 0.f, 0.f);

    issue_chunk<GATE>(0, tid, sA, sB, A0, A1, W, ldw, row0, col0);
    issue_chunk<GATE>(1, tid, sA, sB, A0, A1, W, ldw, row0, col0);
    issue_chunk<GATE>(2, tid, sA, sB, A0, A1, W, ldw, row0, col0);

    for (int kt = 0; kt < NKT; kt++) {
        cp_wait<2>();
        __syncthreads();

        if (kt + 3 < NKT)
            issue_chunk<GATE>(kt + 3, tid, sA, sB, A0, A1, W, ldw, row0, col0);
        else
            CP_COMMIT();

        const int s = kt & (STAGES - 1);
        const uint32_t soff = (uint32_t)(s * 128 * ROWB);

#pragma unroll
        for (int kc = 0; kc < 2; kc++) {
            const uint32_t lbyte = (uint32_t)(lr * ROWB + kc * 32 + lh * 16);
            uint32_t af[4][4];
#pragma unroll
            for (int mt = 0; mt < 4; mt++)
                ldsm_x4(sA + soff + (uint32_t)((m0 + mt * 16) * ROWB) + lbyte, af[mt]);
            uint32_t bf[2][4];
#pragma unroll
            for (int nb = 0; nb < 2; nb++)
                ldsm_x4(sB + soff + (uint32_t)((n0 + nb * 16) * ROWB) + lbyte, bf[nb]);
#pragma unroll
            for (int mt = 0; mt < 4; mt++)
#pragma unroll
                for (int nt = 0; nt < 4; nt++)
                    mma_bf16(acc[mt][nt], af[mt],
                             bf[nt >> 1][nt & 1], bf[nt >> 1][(nt & 1) + 2]);
        }
    }

#pragma unroll
    for (int nt = 0; nt < 4; nt++) {
        int col = col0 + n0 + nt * 8 + 2 * t;
        float bx = bias[col], by = bias[col + 1];
#pragma unroll
        for (int mt = 0; mt < 4; mt++) {
            int r0 = row0 + m0 + mt * 16 + g;
            int r1 = r0 + 8;
            float4 a = acc[mt][nt];
            float v0x = a.x + bx, v0y = a.y + by;
            float v1x = a.z + bx, v1y = a.w + by;
            size_t o0 = (size_t)r0 * 256 + col;
            size_t o1 = (size_t)r1 * 256 + col;
            if (MODE == 0) {
                *(float2*)&C[o0] = make_float2(v0x, v0y);
                *(float2*)&C[o1] = make_float2(v1x, v1y);
            } else if (MODE == 1) {
                *(float2*)&C[o0] = make_float2(v0x, v0y);
                *(float2*)&C[o1] = make_float2(v1x, v1y);
                *(__nv_bfloat162*)&Cbf[o0] = __floats2bfloat162_rn(v0x, v0y);
                *(__nv_bfloat162*)&Cbf[o1] = __floats2bfloat162_rn(v1x, v1y);
            } else if (MODE == 3) {
                *(__nv_bfloat162*)&Cbf[o0] = __floats2bfloat162_rn(v0x, v0y);
                *(__nv_bfloat162*)&Cbf[o1] = __floats2bfloat162_rn(v1x, v1y);
            } else {
                float2 x0 = *(const float2*)&Xf[o0];
                float2 x1 = *(const float2*)&Xf[o1];
                float2 u0 = *(const float2*)&Uf[o0];
                float2 u1 = *(const float2*)&Uf[o1];
                float2 w0, w1;
                w0.x = x0.x + u0.x / (1.f + __expf(-v0x));
                w0.y = x0.y + u0.y / (1.f + __expf(-v0y));
                w1.x = x1.x + u1.x / (1.f + __expf(-v1x));
                w1.y = x1.y + u1.y / (1.f + __expf(-v1y));
                *(float2*)&C[o0] = w0;
                *(float2*)&C[o1] = w1;
            }
        }
    }
}

// ---------------- conversion kernels -----------------------------------------
__global__ void conv_bands(BandPtrs bp)
{
    int z = blockIdx.z;
    int i4 = (blockIdx.x * blockDim.x + threadIdx.x) * 4;
    if (i4 >= SLAB) return;
    float4 v = *(const float4*)&bp.p[z][i4];
    __nv_bfloat16* d = g_band_bf + (size_t)z * SLAB + i4;
    *(__nv_bfloat162*)&d[0] = __floats2bfloat162_rn(v.x, v.y);
    *(__nv_bfloat162*)&d[2] = __floats2bfloat162_rn(v.z, v.w);
}

__global__ void conv_weights(WSrc ws)
{
    const int sizes[7] = {458752, 458752, 458752, 196608, 196608, 65536, 917504};
    const int offs[7]  = {OFF_QW, OFF_KW, OFF_VW, OFF_CW, OFF_CRW, OFF_BW, OFF_GW};
    int z = blockIdx.z;
    int i4 = (blockIdx.x * blockDim.x + threadIdx.x) * 4;
    if (i4 >= sizes[z]) return;
    float4 v = *(const float4*)&ws.p[z][i4];
    __nv_bfloat16* d = g_wbf + offs[z] + i4;
    *(__nv_bfloat162*)&d[0] = __floats2bfloat162_rn(v.x, v.y);
    *(__nv_bfloat162*)&d[2] = __floats2bfloat162_rn(v.z, v.w);
}

// ---------------- K1: QKV projections -> bf16 --------------------------------
__global__ void __launch_bounds__(256)
qkv_gemm(const float* __restrict__ qb, const float* __restrict__ kb,
         const float* __restrict__ vb)
{
    int z = blockIdx.z;
    int n = z / 3, which = z - 3 * n;
    const __nv_bfloat16* A = g_band_bf + (size_t)n * SLAB;
    const __nv_bfloat16* W; const float* bias; __nv_bfloat16* C;
    if (which == 0)      { W = g_wbf + OFF_QW + (size_t)n * 65536; bias = qb + n * 256; C = g_qbf + (size_t)n * SLAB; }
    else if (which == 1) { W = g_wbf + OFF_KW + (size_t)n * 65536; bias = kb + n * 256; C = g_kbf + (size_t)n * SLAB; }
    else                 { W = g_wbf + OFF_VW + (size_t)n * 65536; bias = vb + n * 256; C = g_vbf + (size_t)n * SLAB; }
    gemm_body<3>(A, nullptr, W, 256, bias, nullptr, C, nullptr, nullptr);
}

// ---------------------------------------------------------------------------
// K2: MMA windowed attention, per-band KT (KT/2 must be a multiple of 16),
// split-half K/V smem. Same arithmetic as R13; half-sized smem residency.
// ---------------------------------------------------------------------------

template<int KT>
__global__ void __launch_bounds__(256)
attn_mma(int nbase)
{
    static_assert((KT / 2) % 16 == 0, "KH must be a multiple of 16");
    constexpr int KH   = KT / 2;
    constexpr int KB0  = KT - 64;
    constexpr int QST  = 528;
    constexpr int PST  = KT * 2 + 16;
    constexpr int VW0  = KT / 16 + 1;
    constexpr int VST  = 16 * (VW0 + ((VW0 & 1) ? 0 : 1));
    constexpr int KREG = (KH * QST > 256 * VST) ? KH * QST : 256 * VST;
    constexpr int OFFQ = 0;
    constexpr int OFFK = 64 * QST;
    constexpr int OFFP = OFFK + KREG;
    constexpr int OFFR = OFFP + 64 * PST;

    extern __shared__ char sm[];
    const uint32_t s32 = smem_u32(sm);
    float* rsum = (float*)(sm + OFFR);

    const int n  = nbase + blockIdx.z;
    const int b  = blockIdx.y;
    const int t0 = blockIdx.x * 64;
    const int w  = c_win[n];
    const int kb0 = t0 - KB0;
    const size_t slab = ((size_t)n * M_ROWS + (size_t)b * 1024) * 256;

    const int tid = threadIdx.x, wid = tid >> 5, lane = tid & 31;
    const int g = lane >> 2, t = lane & 3, lr = lane & 15, lh = lane >> 4;

    // ---- load Q once ----
    {
        const __nv_bfloat16* Qg = g_qbf + slab + (size_t)t0 * 256;
#pragma unroll
        for (int i = 0; i < 8; i++) {
            int idx = tid + i * 256; int r = idx >> 5, c = idx & 31;
            cp16(s32 + OFFQ + r * QST + c * 16, Qg + (size_t)r * 256 + c * 8);
        }
    }

    float4 sacc[KT / 8];
#pragma unroll
    for (int i = 0; i < KT / 8; i++) sacc[i] = make_float4(0.f, 0.f, 0.f, 0.f);

    // ---- phase 1: scores, two K halves sharing one smem region ----
#pragma unroll
    for (int h = 0; h < 2; h++) {
        const __nv_bfloat16* Kg = g_kbf + slab;
#pragma unroll
        for (int i = 0; i < KH / 8; i++) {
            int idx = tid + i * 256; int r = idx >> 5, c = idx & 31;
            int jr = kb0 + h * KH + r; jr = jr < 0 ? 0 : jr;
            cp16(s32 + OFFK + r * QST + c * 16, Kg + (size_t)jr * 256 + c * 8);
        }
        CP_COMMIT();
        cp_wait<0>();
        __syncthreads();

        if (wid < 4) {
            const int m0 = wid * 16;
#pragma unroll
            for (int kc = 0; kc < 16; kc++) {
                uint32_t af[4];
                ldsm_x4(s32 + OFFQ + (m0 + lr) * QST + kc * 32 + lh * 16, af);
#pragma unroll
                for (int nb = 0; nb < KH / 16; nb++) {
                    uint32_t bf[4];
                    ldsm_x4(s32 + OFFK + (nb * 16 + lr) * QST + kc * 32 + lh * 16, bf);
                    mma_bf16(sacc[h * (KH / 8) + 2 * nb],     af, bf[0], bf[2]);
                    mma_bf16(sacc[h * (KH / 8) + 2 * nb + 1], af, bf[1], bf[3]);
                }
            }
        }
        __syncthreads();
    }

    // ---- phase 2: masked softmax (warps 0-3), write P + rsum ----
    if (wid < 4) {
        const int m0 = wid * 16;
        const int tq0 = t0 + m0 + g, tq1 = tq0 + 8;
        const int lo0 = max(0, tq0 - w + 1), lo1 = max(0, tq1 - w + 1);
        const float scale = 0.0625f;
        float mx0 = -1e30f, mx1 = -1e30f;
#pragma unroll
        for (int nt = 0; nt < KT / 8; nt++) {
            int jg = kb0 + nt * 8 + 2 * t;
            float4 s = sacc[nt];
            s.x = (jg     >= lo0 && jg     <= tq0) ? s.x * scale : -1e30f;
            s.y = (jg + 1 >= lo0 && jg + 1 <= tq0) ? s.y * scale : -1e30f;
            s.z = (jg     >= lo1 && jg     <= tq1) ? s.z * scale : -1e30f;
            s.w = (jg + 1 >= lo1 && jg + 1 <= tq1) ? s.w * scale : -1e30f;
            sacc[nt] = s;
            mx0 = fmaxf(mx0, fmaxf(s.x, s.y));
            mx1 = fmaxf(mx1, fmaxf(s.z, s.w));
        }
        mx0 = fmaxf(mx0, __shfl_xor_sync(0xffffffffu, mx0, 1));
        mx0 = fmaxf(mx0, __shfl_xor_sync(0xffffffffu, mx0, 2));
        mx1 = fmaxf(mx1, __shfl_xor_sync(0xffffffffu, mx1, 1));
        mx1 = fmaxf(mx1, __shfl_xor_sync(0xffffffffu, mx1, 2));

        float sum0 = 0.f, sum1 = 0.f;
#pragma unroll
        for (int nt = 0; nt < KT / 8; nt++) {
            float4 s = sacc[nt];
            float e0 = __expf(s.x - mx0), e1 = __expf(s.y - mx0);
            float e2 = __expf(s.z - mx1), e3 = __expf(s.w - mx1);
            sum0 += e0 + e1; sum1 += e2 + e3;
            char* p0 = sm + OFFP + (m0 + g) * PST + (nt * 8 + 2 * t) * 2;
            *(__nv_bfloat162*)p0             = __floats2bfloat162_rn(e0, e1);
            *(__nv_bfloat162*)(p0 + 8 * PST) = __floats2bfloat162_rn(e2, e3);
        }
        sum0 += __shfl_xor_sync(0xffffffffu, sum0, 1);
        sum0 += __shfl_xor_sync(0xffffffffu, sum0, 2);
        sum1 += __shfl_xor_sync(0xffffffffu, sum1, 1);
        sum1 += __shfl_xor_sync(0xffffffffu, sum1, 2);
        if (t == 0) {
            rsum[m0 + g]     = 1.f / sum0;
            rsum[m0 + g + 8] = 1.f / sum1;
        }
    }
    __syncthreads();

    // ---- phase 3: O = P @ Vt^T, two V halves ----
    const int m0o = (wid & 3) * 16;
    const int n0o = (wid >> 2) * 128;
    float4 oacc[16];
#pragma unroll
    for (int i = 0; i < 16; i++) oacc[i] = make_float4(0.f, 0.f, 0.f, 0.f);

#pragma unroll
    for (int h = 0; h < 2; h++) {
        const __nv_bfloat16* Vg = g_vbf + slab;
#pragma unroll
        for (int i = 0; i < KH / 16; i++) {
            int tt = tid + i * 256;
            int jp = tt % (KH / 2), dc = tt / (KH / 2);
            int j0 = 2 * jp;
            int r0c = kb0 + h * KH + j0;     r0c = r0c < 0 ? 0 : (r0c > 1023 ? 1023 : r0c);
            int r1c = kb0 + h * KH + j0 + 1; r1c = r1c < 0 ? 0 : (r1c > 1023 ? 1023 : r1c);
            uint4 u0 = *(const uint4*)(Vg + (size_t)r0c * 256 + dc * 8);
            uint4 u1 = *(const uint4*)(Vg + (size_t)r1c * 256 + dc * 8);
            const __nv_bfloat16* p0 = (const __nv_bfloat16*)&u0;
            const __nv_bfloat16* p1 = (const __nv_bfloat16*)&u1;
#pragma unroll
            for (int e = 0; e < 8; e++) {
                __nv_bfloat162 pv;
                pv.x = p0[e]; pv.y = p1[e];
                *(__nv_bfloat162*)(sm + OFFK + (dc * 8 + e) * VST + j0 * 2) = pv;
            }
        }
        __syncthreads();

#pragma unroll
        for (int kc = 0; kc < KH / 16; kc++) {
            uint32_t af[4];
            ldsm_x4(s32 + OFFP + (m0o + lr) * PST + h * KH * 2 + kc * 32 + lh * 16, af);
#pragma unroll
            for (int nb = 0; nb < 8; nb++) {
                uint32_t bf[4];
                ldsm_x4(s32 + OFFK + (n0o + nb * 16 + lr) * VST + kc * 32 + lh * 16, bf);
                mma_bf16(oacc[2 * nb],     af, bf[0], bf[2]);
                mma_bf16(oacc[2 * nb + 1], af, bf[1], bf[3]);
            }
        }
        __syncthreads();
    }

    {
        const float i0 = rsum[m0o + g], i1 = rsum[m0o + g + 8];
        __nv_bfloat16* Cg = g_ctx_bf + slab + (size_t)(t0 + m0o + g) * 256;
#pragma unroll
        for (int nt = 0; nt < 16; nt++) {
            int col = n0o + nt * 8 + 2 * t;
            float4 o = oacc[nt];
            *(__nv_bfloat162*)&Cg[col]           = __floats2bfloat162_rn(o.x * i0, o.y * i0);
            *(__nv_bfloat162*)&Cg[8 * 256 + col] = __floats2bfloat162_rn(o.z * i1, o.w * i1);
        }
    }
}

// ---------------- K3: other = mean of ctx over bands != 3 -------------------
__global__ void other_kernel()
{
    int i4 = (blockIdx.x * blockDim.x + threadIdx.x) * 4;
    if (i4 >= SLAB) return;
    float4 s = {0.f, 0.f, 0.f, 0.f};
#pragma unroll
    for (int nn = 0; nn < 7; nn++) {
        if (nn == 3) continue;
        const __nv_bfloat162* p = (const __nv_bfloat162*)&g_ctx_bf[(size_t)nn * SLAB + i4];
        float2 a = __bfloat1622float2(p[0]);
        float2 b = __bfloat1622float2(p[1]);
        s.x += a.x; s.y += a.y; s.z += b.x; s.w += b.y;
    }
    const float k = 1.f / 6.f;
    __nv_bfloat16* d = g_other_bf + i4;
    *(__nv_bfloat162*)&d[0] = __floats2bfloat162_rn(s.x * k, s.y * k);
    *(__nv_bfloat162*)&d[2] = __floats2bfloat162_rn(s.z * k, s.w * k);
}

// ---------------- K4: per-band update projections u[n] (fp32 + bf16) --------
__global__ void __launch_bounds__(256)
u_gemm(const float* __restrict__ crossb, const float* __restrict__ crossrb,
       const float* __restrict__ bridgeb)
{
    int n = blockIdx.z;
    const __nv_bfloat16 *A, *W; const float* bias;
    switch (n) {
        case 0:  A = g_ctx_bf + (size_t)6 * SLAB; W = g_wbf + OFF_CRW;             bias = crossrb;       break;
        case 1:  A = g_ctx_bf + (size_t)5 * SLAB; W = g_wbf + OFF_CRW + 65536;     bias = crossrb + 256; break;
        case 2:  A = g_ctx_bf + (size_t)4 * SLAB; W = g_wbf + OFF_CRW + 2 * 65536; bias = crossrb + 512; break;
        case 3:  A = g_other_bf;                  W = g_wbf + OFF_BW;              bias = bridgeb;       break;
        case 4:  A = g_ctx_bf + (size_t)2 * SLAB; W = g_wbf + OFF_CW + 2 * 65536;  bias = crossb + 512;  break;
        case 5:  A = g_ctx_bf + (size_t)1 * SLAB; W = g_wbf + OFF_CW + 65536;      bias = crossb + 256;  break;
        default: A = g_ctx_bf;                    W = g_wbf + OFF_CW;              bias = crossb;        break;
    }
    gemm_body<1>(A, nullptr, W, 256, bias,
                 g_u + (size_t)n * SLAB, g_u_bf + (size_t)n * SLAB, nullptr, nullptr);
}

// ---------------- K5: gate GEMM (K=512) + sigmoid + residual ----------------
__global__ void __launch_bounds__(256)
gate_gemm(BandPtrs bp, const float* __restrict__ gateb, float* __restrict__ out)
{
    int n = blockIdx.z;
    gemm_body<2>(g_band_bf + (size_t)n * SLAB, g_u_bf + (size_t)n * SLAB,
                 g_wbf + OFF_GW + (size_t)n * 131072, 512,
                 gateb + n * 256,
                 out + (size_t)n * SLAB, nullptr,
                 bp.p[n], g_u + (size_t)n * SLAB);
}

// ---------------------------------------------------------------------------
extern "C" void kernel_launch(void* const* d_in, const int* in_sizes, int n_in,
                              void* d_out, int out_size)
{
    BandPtrs bp;
    for (int i = 0; i < 7; i++) bp.p[i] = (const float*)d_in[i];
    const float* qb      = (const float*)d_in[8];
    const float* kb      = (const float*)d_in[10];
    const float* vb      = (const float*)d_in[12];
    const float* crossb  = (const float*)d_in[14];
    const float* crossrb = (const float*)d_in[16];
    const float* gateb   = (const float*)d_in[18];
    const float* bridgeb = (const float*)d_in[20];

    WSrc ws;
    ws.p[0] = (const float*)d_in[7];
    ws.p[1] = (const float*)d_in[9];
    ws.p[2] = (const float*)d_in[11];
    ws.p[3] = (const float*)d_in[13];
    ws.p[4] = (const float*)d_in[15];
    ws.p[5] = (const float*)d_in[19];
    ws.p[6] = (const float*)d_in[17];
    float* out = (float*)d_out;

    auto smem_of = [](int KT) {
        int KH = KT / 2;
        int PST = KT * 2 + 16;
        int VW0 = KT / 16 + 1;
        int VST = 16 * (VW0 + ((VW0 & 1) ? 0 : 1));
        int kreg = (KH * 528 > 256 * VST) ? KH * 528 : 256 * VST;
        return 64 * 528 + kreg + 64 * PST + 256;
    };
    const int smem192 = smem_of(192);
    const int smem128 = smem_of(128);
    const int smem96  = smem_of(96);
    cudaFuncSetAttribute(attn_mma<192>, cudaFuncAttributeMaxDynamicSharedMemorySize, smem192);
    cudaFuncSetAttribute(attn_mma<128>, cudaFuncAttributeMaxDynamicSharedMemorySize, smem128);
    cudaFuncSetAttribute(attn_mma<96>,  cudaFuncAttributeMaxDynamicSharedMemorySize, smem96);

    conv_bands<<<dim3(SLAB / 1024, 1, 7), 256>>>(bp);
    conv_weights<<<dim3(917504 / 1024, 1, 7), 256>>>(ws);

    qkv_gemm<<<dim3(M_ROWS / 128, 2, 21), 256>>>(qb, kb, vb);

    attn_mma<192><<<dim3(16, 8, 1), 256, smem192>>>(0);  // band 0 (w=128)
    attn_mma<128><<<dim3(16, 8, 1), 256, smem128>>>(1);  // band 1 (w=64)
    attn_mma<96> <<<dim3(16, 8, 5), 256, smem96 >>>(2);  // bands 2-6 (w<=32)

    other_kernel<<<SLAB / 1024, 256>>>();
    u_gemm<<<dim3(M_ROWS / 128, 2, 7), 256>>>(crossb, crossrb, bridgeb);
    gate_gemm<<<dim3(M_ROWS / 128, 2, 7), 256>>>(bp, gateb, out);
}

// round 16
// speedup vs baseline: 1.0431x; 1.0431x over previous
#include <cuda_runtime.h>
#include <cuda_bf16.h>
#include <math.h>
#include <stdint.h>

// ---------------------------------------------------------------------------
// TemporalWormhole: bf16 m16n8k16 mma.sync GEMMs (R9/R13 core) + single-launch
// MMA flash attention (per-band KT dispatch, split-half K/V smem, 2 CTAs/SM).
// B=8, T=1024, D=256. M = 8192 tokens/band.
// ---------------------------------------------------------------------------

#define D_DIM   256
#define M_ROWS  8192
#define SLAB    (M_ROWS * D_DIM)

__device__ float g_u[7 * SLAB];

__device__ __nv_bfloat16 g_qbf[7 * SLAB];
__device__ __nv_bfloat16 g_kbf[7 * SLAB];
__device__ __nv_bfloat16 g_vbf[7 * SLAB];
__device__ __nv_bfloat16 g_band_bf[7 * SLAB];
__device__ __nv_bfloat16 g_ctx_bf[7 * SLAB];
__device__ __nv_bfloat16 g_u_bf[7 * SLAB];
__device__ __nv_bfloat16 g_other_bf[SLAB];

#define OFF_QW  0
#define OFF_KW  458752
#define OFF_VW  917504
#define OFF_CW  1376256
#define OFF_CRW 1572864
#define OFF_BW  1769472
#define OFF_GW  1835008
__device__ __nv_bfloat16 g_wbf[2752512];

__constant__ int c_win[7] = {128, 64, 32, 16, 16, 8, 4};

struct BandPtrs { const float* p[7]; };
struct WSrc     { const float* p[7]; };

// ---------------------------- PTX helpers -----------------------------------
__device__ __forceinline__ uint32_t smem_u32(const void* p) {
    uint32_t a;
    asm("{ .reg .u64 t; cvta.to.shared.u64 t, %1; cvt.u32.u64 %0, t; }"
        : "=r"(a) : "l"(p));
    return a;
}

__device__ __forceinline__ void cp16(uint32_t dst, const void* src) {
    asm volatile("cp.async.cg.shared.global [%0], [%1], 16;"
                 :: "r"(dst), "l"(src) : "memory");
}
#define CP_COMMIT() asm volatile("cp.async.commit_group;" ::: "memory")
template<int N>
__device__ __forceinline__ void cp_wait() {
    asm volatile("cp.async.wait_group %0;" :: "n"(N) : "memory");
}

__device__ __forceinline__ void ldsm_x4(uint32_t addr, uint32_t r[4]) {
    asm volatile("ldmatrix.sync.aligned.m8n8.x4.shared.b16 {%0,%1,%2,%3}, [%4];"
        : "=r"(r[0]), "=r"(r[1]), "=r"(r[2]), "=r"(r[3]) : "r"(addr));
}

__device__ __forceinline__ void mma_bf16(float4& d, const uint32_t a[4],
                                         uint32_t b0, uint32_t b1) {
    asm volatile(
        "mma.sync.aligned.m16n8k16.row.col.f32.bf16.bf16.f32 "
        "{%0,%1,%2,%3}, {%4,%5,%6,%7}, {%8,%9}, {%0,%1,%2,%3};"
        : "+f"(d.x), "+f"(d.y), "+f"(d.z), "+f"(d.w)
        : "r"(a[0]), "r"(a[1]), "r"(a[2]), "r"(a[3]), "r"(b0), "r"(b1));
}

// ---------------------------------------------------------------------------
// bf16 GEMM (exact R9/R13 core).
// ---------------------------------------------------------------------------

#define STAGES 4
#define ROWB   80

template<bool GATE>
__device__ __forceinline__ void issue_chunk(
    int kn, int tid, uint32_t sA, uint32_t sB,
    const __nv_bfloat16* __restrict__ A0, const __nv_bfloat16* __restrict__ A1,
    const __nv_bfloat16* __restrict__ W, int ldw, int row0, int col0)
{
    const __nv_bfloat16* Ab; int k0;
    if (GATE && kn >= 8) { Ab = A1; k0 = (kn - 8) * 32; }
    else                 { Ab = A0; k0 = kn * 32; }
    const int kw0 = kn * 32;
    const int s   = kn & (STAGES - 1);
#pragma unroll
    for (int i = 0; i < 2; i++) {
        int idx = tid + i * 256;
        int r = idx >> 2, q = idx & 3;
        uint32_t off = (uint32_t)((s * 128 + r) * ROWB + q * 16);
        cp16(sA + off, Ab + (size_t)(row0 + r) * 256 + k0 + q * 8);
        cp16(sB + off, W + (size_t)(col0 + r) * ldw + kw0 + q * 8);
    }
    CP_COMMIT();
}

template<int MODE>
__device__ __forceinline__ void gemm_body(
    const __nv_bfloat16* __restrict__ A0,
    const __nv_bfloat16* __restrict__ A1,
    const __nv_bfloat16* __restrict__ W, int ldw,
    const float* __restrict__ bias,
    float* __restrict__ C,
    __nv_bfloat16* __restrict__ Cbf,
    const float* __restrict__ Xf,
    const float* __restrict__ Uf)
{
    const bool GATE = (MODE == 2);
    const int NKT = GATE ? 16 : 8;
    __shared__ __align__(16) __nv_bfloat16 smA[STAGES * 128 * 40];
    __shared__ __align__(16) __nv_bfloat16 smB[STAGES * 128 * 40];

    const int tid  = threadIdx.x;
    const int wid  = tid >> 5;
    const int lane = tid & 31;
    const int g    = lane >> 2;
    const int t    = lane & 3;
    const int m0   = (wid & 1) * 64;
    const int n0   = (wid >> 1) * 32;
    const int row0 = blockIdx.x * 128;
    const int col0 = blockIdx.y * 128;
    const int lr   = lane & 15;
    const int lh   = lane >> 4;

    const uint32_t sA = smem_u32(smA);
    const uint32_t sB = smem_u32(smB);

    float4 acc[4][4];
#pragma unroll
    for (int mt = 0; mt < 4; mt++)
#pragma unroll
        for (int nt = 0; nt < 4; nt++) acc[mt][nt] = make_float4(0.f, 0.f, 0.f, 0.f);

    issue_chunk<GATE>(0, tid, sA, sB, A0, A1, W, ldw, row0, col0);
    issue_chunk<GATE>(1, tid, sA, sB, A0, A1, W, ldw, row0, col0);
    issue_chunk<GATE>(2, tid, sA, sB, A0, A1, W, ldw, row0, col0);

    for (int kt = 0; kt < NKT; kt++) {
        cp_wait<2>();
        __syncthreads();

        if (kt + 3 < NKT)
            issue_chunk<GATE>(kt + 3, tid, sA, sB, A0, A1, W, ldw, row0, col0);
        else
            CP_COMMIT();

        const int s = kt & (STAGES - 1);
        const uint32_t soff = (uint32_t)(s * 128 * ROWB);

#pragma unroll
        for (int kc = 0; kc < 2; kc++) {
            const uint32_t lbyte = (uint32_t)(lr * ROWB + kc * 32 + lh * 16);
            uint32_t af[4][4];
#pragma unroll
            for (int mt = 0; mt < 4; mt++)
                ldsm_x4(sA + soff + (uint32_t)((m0 + mt * 16) * ROWB) + lbyte, af[mt]);
            uint32_t bf[2][4];
#pragma unroll
            for (int nb = 0; nb < 2; nb++)
                ldsm_x4(sB + soff + (uint32_t)((n0 + nb * 16) * ROWB) + lbyte, bf[nb]);
#pragma unroll
            for (int mt = 0; mt < 4; mt++)
#pragma unroll
                for (int nt = 0; nt < 4; nt++)
                    mma_bf16(acc[mt][nt], af[mt],
                             bf[nt >> 1][nt & 1], bf[nt >> 1][(nt & 1) + 2]);
        }
    }

#pragma unroll
    for (int nt = 0; nt < 4; nt++) {
        int col = col0 + n0 + nt * 8 + 2 * t;
        float bx = bias[col], by = bias[col + 1];
#pragma unroll
        for (int mt = 0; mt < 4; mt++) {
            int r0 = row0 + m0 + mt * 16 + g;
            int r1 = r0 + 8;
            float4 a = acc[mt][nt];
            float v0x = a.x + bx, v0y = a.y + by;
            float v1x = a.z + bx, v1y = a.w + by;
            size_t o0 = (size_t)r0 * 256 + col;
            size_t o1 = (size_t)r1 * 256 + col;
            if (MODE == 0) {
                *(float2*)&C[o0] = make_float2(v0x, v0y);
                *(float2*)&C[o1] = make_float2(v1x, v1y);
            } else if (MODE == 1) {
                *(float2*)&C[o0] = make_float2(v0x, v0y);
                *(float2*)&C[o1] = make_float2(v1x, v1y);
                *(__nv_bfloat162*)&Cbf[o0] = __floats2bfloat162_rn(v0x, v0y);
                *(__nv_bfloat162*)&Cbf[o1] = __floats2bfloat162_rn(v1x, v1y);
            } else if (MODE == 3) {
                *(__nv_bfloat162*)&Cbf[o0] = __floats2bfloat162_rn(v0x, v0y);
                *(__nv_bfloat162*)&Cbf[o1] = __floats2bfloat162_rn(v1x, v1y);
            } else {
                float2 x0 = *(const float2*)&Xf[o0];
                float2 x1 = *(const float2*)&Xf[o1];
                float2 u0 = *(const float2*)&Uf[o0];
                float2 u1 = *(const float2*)&Uf[o1];
                float2 w0, w1;
                w0.x = x0.x + u0.x / (1.f + __expf(-v0x));
                w0.y = x0.y + u0.y / (1.f + __expf(-v0y));
                w1.x = x1.x + u1.x / (1.f + __expf(-v1x));
                w1.y = x1.y + u1.y / (1.f + __expf(-v1y));
                *(float2*)&C[o0] = w0;
                *(float2*)&C[o1] = w1;
            }
        }
    }
}

// ---------------- conversion kernels -----------------------------------------
__global__ void conv_bands(BandPtrs bp)
{
    int z = blockIdx.z;
    int i4 = (blockIdx.x * blockDim.x + threadIdx.x) * 4;
    if (i4 >= SLAB) return;
    float4 v = *(const float4*)&bp.p[z][i4];
    __nv_bfloat16* d = g_band_bf + (size_t)z * SLAB + i4;
    *(__nv_bfloat162*)&d[0] = __floats2bfloat162_rn(v.x, v.y);
    *(__nv_bfloat162*)&d[2] = __floats2bfloat162_rn(v.z, v.w);
}

__global__ void conv_weights(WSrc ws)
{
    const int sizes[7] = {458752, 458752, 458752, 196608, 196608, 65536, 917504};
    const int offs[7]  = {OFF_QW, OFF_KW, OFF_VW, OFF_CW, OFF_CRW, OFF_BW, OFF_GW};
    int z = blockIdx.z;
    int i4 = (blockIdx.x * blockDim.x + threadIdx.x) * 4;
    if (i4 >= sizes[z]) return;
    float4 v = *(const float4*)&ws.p[z][i4];
    __nv_bfloat16* d = g_wbf + offs[z] + i4;
    *(__nv_bfloat162*)&d[0] = __floats2bfloat162_rn(v.x, v.y);
    *(__nv_bfloat162*)&d[2] = __floats2bfloat162_rn(v.z, v.w);
}

// ---------------- K1: QKV projections -> bf16 --------------------------------
__global__ void __launch_bounds__(256)
qkv_gemm(const float* __restrict__ qb, const float* __restrict__ kb,
         const float* __restrict__ vb)
{
    int z = blockIdx.z;
    int n = z / 3, which = z - 3 * n;
    const __nv_bfloat16* A = g_band_bf + (size_t)n * SLAB;
    const __nv_bfloat16* W; const float* bias; __nv_bfloat16* C;
    if (which == 0)      { W = g_wbf + OFF_QW + (size_t)n * 65536; bias = qb + n * 256; C = g_qbf + (size_t)n * SLAB; }
    else if (which == 1) { W = g_wbf + OFF_KW + (size_t)n * 65536; bias = kb + n * 256; C = g_kbf + (size_t)n * SLAB; }
    else                 { W = g_wbf + OFF_VW + (size_t)n * 65536; bias = vb + n * 256; C = g_vbf + (size_t)n * SLAB; }
    gemm_body<3>(A, nullptr, W, 256, bias, nullptr, C, nullptr, nullptr);
}

// ---------------------------------------------------------------------------
// K2: attention body (split-half K/V smem, R15-exact math), per-band KT.
// ---------------------------------------------------------------------------

template<int KT>
__device__ __forceinline__ void attn_body(int n, int b, int t0)
{
    static_assert((KT / 2) % 16 == 0, "KH must be a multiple of 16");
    constexpr int KH   = KT / 2;
    constexpr int KB0  = KT - 64;
    constexpr int QST  = 528;
    constexpr int PST  = KT * 2 + 16;
    constexpr int VW0  = KT / 16 + 1;
    constexpr int VST  = 16 * (VW0 + ((VW0 & 1) ? 0 : 1));
    constexpr int KREG = (KH * QST > 256 * VST) ? KH * QST : 256 * VST;
    constexpr int OFFQ = 0;
    constexpr int OFFK = 64 * QST;
    constexpr int OFFP = OFFK + KREG;
    constexpr int OFFR = OFFP + 64 * PST;

    extern __shared__ char sm[];
    const uint32_t s32 = smem_u32(sm);
    float* rsum = (float*)(sm + OFFR);

    const int w  = c_win[n];
    const int kb0 = t0 - KB0;
    const size_t slab = ((size_t)n * M_ROWS + (size_t)b * 1024) * 256;

    const int tid = threadIdx.x, wid = tid >> 5, lane = tid & 31;
    const int g = lane >> 2, t = lane & 3, lr = lane & 15, lh = lane >> 4;

    // ---- load Q once ----
    {
        const __nv_bfloat16* Qg = g_qbf + slab + (size_t)t0 * 256;
#pragma unroll
        for (int i = 0; i < 8; i++) {
            int idx = tid + i * 256; int r = idx >> 5, c = idx & 31;
            cp16(s32 + OFFQ + r * QST + c * 16, Qg + (size_t)r * 256 + c * 8);
        }
    }

    float4 sacc[KT / 8];
#pragma unroll
    for (int i = 0; i < KT / 8; i++) sacc[i] = make_float4(0.f, 0.f, 0.f, 0.f);

    // ---- phase 1: scores, two K halves ----
#pragma unroll
    for (int h = 0; h < 2; h++) {
        const __nv_bfloat16* Kg = g_kbf + slab;
#pragma unroll
        for (int i = 0; i < KH / 8; i++) {
            int idx = tid + i * 256; int r = idx >> 5, c = idx & 31;
            int jr = kb0 + h * KH + r; jr = jr < 0 ? 0 : jr;
            cp16(s32 + OFFK + r * QST + c * 16, Kg + (size_t)jr * 256 + c * 8);
        }
        CP_COMMIT();
        cp_wait<0>();
        __syncthreads();

        if (wid < 4) {
            const int m0 = wid * 16;
#pragma unroll
            for (int kc = 0; kc < 16; kc++) {
                uint32_t af[4];
                ldsm_x4(s32 + OFFQ + (m0 + lr) * QST + kc * 32 + lh * 16, af);
#pragma unroll
                for (int nb = 0; nb < KH / 16; nb++) {
                    uint32_t bf[4];
                    ldsm_x4(s32 + OFFK + (nb * 16 + lr) * QST + kc * 32 + lh * 16, bf);
                    mma_bf16(sacc[h * (KH / 8) + 2 * nb],     af, bf[0], bf[2]);
                    mma_bf16(sacc[h * (KH / 8) + 2 * nb + 1], af, bf[1], bf[3]);
                }
            }
        }
        __syncthreads();
    }

    // ---- phase 2: masked softmax ----
    if (wid < 4) {
        const int m0 = wid * 16;
        const int tq0 = t0 + m0 + g, tq1 = tq0 + 8;
        const int lo0 = max(0, tq0 - w + 1), lo1 = max(0, tq1 - w + 1);
        const float scale = 0.0625f;
        float mx0 = -1e30f, mx1 = -1e30f;
#pragma unroll
        for (int nt = 0; nt < KT / 8; nt++) {
            int jg = kb0 + nt * 8 + 2 * t;
            float4 s = sacc[nt];
            s.x = (jg     >= lo0 && jg     <= tq0) ? s.x * scale : -1e30f;
            s.y = (jg + 1 >= lo0 && jg + 1 <= tq0) ? s.y * scale : -1e30f;
            s.z = (jg     >= lo1 && jg     <= tq1) ? s.z * scale : -1e30f;
            s.w = (jg + 1 >= lo1 && jg + 1 <= tq1) ? s.w * scale : -1e30f;
            sacc[nt] = s;
            mx0 = fmaxf(mx0, fmaxf(s.x, s.y));
            mx1 = fmaxf(mx1, fmaxf(s.z, s.w));
        }
        mx0 = fmaxf(mx0, __shfl_xor_sync(0xffffffffu, mx0, 1));
        mx0 = fmaxf(mx0, __shfl_xor_sync(0xffffffffu, mx0, 2));
        mx1 = fmaxf(mx1, __shfl_xor_sync(0xffffffffu, mx1, 1));
        mx1 = fmaxf(mx1, __shfl_xor_sync(0xffffffffu, mx1, 2));

        float sum0 = 0.f, sum1 = 0.f;
#pragma unroll
        for (int nt = 0; nt < KT / 8; nt++) {
            float4 s = sacc[nt];
            float e0 = __expf(s.x - mx0), e1 = __expf(s.y - mx0);
            float e2 = __expf(s.z - mx1), e3 = __expf(s.w - mx1);
            sum0 += e0 + e1; sum1 += e2 + e3;
            char* p0 = sm + OFFP + (m0 + g) * PST + (nt * 8 + 2 * t) * 2;
            *(__nv_bfloat162*)p0             = __floats2bfloat162_rn(e0, e1);
            *(__nv_bfloat162*)(p0 + 8 * PST) = __floats2bfloat162_rn(e2, e3);
        }
        sum0 += __shfl_xor_sync(0xffffffffu, sum0, 1);
        sum0 += __shfl_xor_sync(0xffffffffu, sum0, 2);
        sum1 += __shfl_xor_sync(0xffffffffu, sum1, 1);
        sum1 += __shfl_xor_sync(0xffffffffu, sum1, 2);
        if (t == 0) {
            rsum[m0 + g]     = 1.f / sum0;
            rsum[m0 + g + 8] = 1.f / sum1;
        }
    }
    __syncthreads();

    // ---- phase 3: O = P @ Vt^T, two V halves ----
    const int m0o = (wid & 3) * 16;
    const int n0o = (wid >> 2) * 128;
    float4 oacc[16];
#pragma unroll
    for (int i = 0; i < 16; i++) oacc[i] = make_float4(0.f, 0.f, 0.f, 0.f);

#pragma unroll
    for (int h = 0; h < 2; h++) {
        const __nv_bfloat16* Vg = g_vbf + slab;
#pragma unroll
        for (int i = 0; i < KH / 16; i++) {
            int tt = tid + i * 256;
            int jp = tt % (KH / 2), dc = tt / (KH / 2);
            int j0 = 2 * jp;
            int r0c = kb0 + h * KH + j0;     r0c = r0c < 0 ? 0 : (r0c > 1023 ? 1023 : r0c);
            int r1c = kb0 + h * KH + j0 + 1; r1c = r1c < 0 ? 0 : (r1c > 1023 ? 1023 : r1c);
            uint4 u0 = *(const uint4*)(Vg + (size_t)r0c * 256 + dc * 8);
            uint4 u1 = *(const uint4*)(Vg + (size_t)r1c * 256 + dc * 8);
            const __nv_bfloat16* p0 = (const __nv_bfloat16*)&u0;
            const __nv_bfloat16* p1 = (const __nv_bfloat16*)&u1;
#pragma unroll
            for (int e = 0; e < 8; e++) {
                __nv_bfloat162 pv;
                pv.x = p0[e]; pv.y = p1[e];
                *(__nv_bfloat162*)(sm + OFFK + (dc * 8 + e) * VST + j0 * 2) = pv;
            }
        }
        __syncthreads();

#pragma unroll
        for (int kc = 0; kc < KH / 16; kc++) {
            uint32_t af[4];
            ldsm_x4(s32 + OFFP + (m0o + lr) * PST + h * KH * 2 + kc * 32 + lh * 16, af);
#pragma unroll
            for (int nb = 0; nb < 8; nb++) {
                uint32_t bf[4];
                ldsm_x4(s32 + OFFK + (n0o + nb * 16 + lr) * VST + kc * 32 + lh * 16, bf);
                mma_bf16(oacc[2 * nb],     af, bf[0], bf[2]);
                mma_bf16(oacc[2 * nb + 1], af, bf[1], bf[3]);
            }
        }
        __syncthreads();
    }

    {
        const float i0 = rsum[m0o + g], i1 = rsum[m0o + g + 8];
        __nv_bfloat16* Cg = g_ctx_bf + slab + (size_t)(t0 + m0o + g) * 256;
#pragma unroll
        for (int nt = 0; nt < 16; nt++) {
            int col = n0o + nt * 8 + 2 * t;
            float4 o = oacc[nt];
            *(__nv_bfloat162*)&Cg[col]           = __floats2bfloat162_rn(o.x * i0, o.y * i0);
            *(__nv_bfloat162*)&Cg[8 * 256 + col] = __floats2bfloat162_rn(o.z * i1, o.w * i1);
        }
    }
}

// Single-launch attention: grid (16, 8, 7); per-band KT dispatch.
__global__ void __launch_bounds__(256, 2)
attn_all()
{
    const int n  = blockIdx.z;
    const int b  = blockIdx.y;
    const int t0 = blockIdx.x * 64;
    if (n == 0)      attn_body<192>(n, b, t0);
    else if (n == 1) attn_body<128>(n, b, t0);
    else             attn_body<96>(n, b, t0);
}

// ---------------- K3: other = mean of ctx over bands != 3 -------------------
__global__ void other_kernel()
{
    int i4 = (blockIdx.x * blockDim.x + threadIdx.x) * 4;
    if (i4 >= SLAB) return;
    float4 s = {0.f, 0.f, 0.f, 0.f};
#pragma unroll
    for (int nn = 0; nn < 7; nn++) {
        if (nn == 3) continue;
        const __nv_bfloat162* p = (const __nv_bfloat162*)&g_ctx_bf[(size_t)nn * SLAB + i4];
        float2 a = __bfloat1622float2(p[0]);
        float2 b = __bfloat1622float2(p[1]);
        s.x += a.x; s.y += a.y; s.z += b.x; s.w += b.y;
    }
    const float k = 1.f / 6.f;
    __nv_bfloat16* d = g_other_bf + i4;
    *(__nv_bfloat162*)&d[0] = __floats2bfloat162_rn(s.x * k, s.y * k);
    *(__nv_bfloat162*)&d[2] = __floats2bfloat162_rn(s.z * k, s.w * k);
}

// ---------------- K4: per-band update projections u[n] (fp32 + bf16) --------
__global__ void __launch_bounds__(256)
u_gemm(const float* __restrict__ crossb, const float* __restrict__ crossrb,
       const float* __restrict__ bridgeb)
{
    int n = blockIdx.z;
    const __nv_bfloat16 *A, *W; const float* bias;
    switch (n) {
        case 0:  A = g_ctx_bf + (size_t)6 * SLAB; W = g_wbf + OFF_CRW;             bias = crossrb;       break;
        case 1:  A = g_ctx_bf + (size_t)5 * SLAB; W = g_wbf + OFF_CRW + 65536;     bias = crossrb + 256; break;
        case 2:  A = g_ctx_bf + (size_t)4 * SLAB; W = g_wbf + OFF_CRW + 2 * 65536; bias = crossrb + 512; break;
        case 3:  A = g_other_bf;                  W = g_wbf + OFF_BW;              bias = bridgeb;       break;
        case 4:  A = g_ctx_bf + (size_t)2 * SLAB; W = g_wbf + OFF_CW + 2 * 65536;  bias = crossb + 512;  break;
        case 5:  A = g_ctx_bf + (size_t)1 * SLAB; W = g_wbf + OFF_CW + 65536;      bias = crossb + 256;  break;
        default: A = g_ctx_bf;                    W = g_wbf + OFF_CW;              bias = crossb;        break;
    }
    gemm_body<1>(A, nullptr, W, 256, bias,
                 g_u + (size_t)n * SLAB, g_u_bf + (size_t)n * SLAB, nullptr, nullptr);
}

// ---------------- K5: gate GEMM (K=512) + sigmoid + residual ----------------
__global__ void __launch_bounds__(256)
gate_gemm(BandPtrs bp, const float* __restrict__ gateb, float* __restrict__ out)
{
    int n = blockIdx.z;
    gemm_body<2>(g_band_bf + (size_t)n * SLAB, g_u_bf + (size_t)n * SLAB,
                 g_wbf + OFF_GW + (size_t)n * 131072, 512,
                 gateb + n * 256,
                 out + (size_t)n * SLAB, nullptr,
                 bp.p[n], g_u + (size_t)n * SLAB);
}

// ---------------------------------------------------------------------------
extern "C" void kernel_launch(void* const* d_in, const int* in_sizes, int n_in,
                              void* d_out, int out_size)
{
    BandPtrs bp;
    for (int i = 0; i < 7; i++) bp.p[i] = (const float*)d_in[i];
    const float* qb      = (const float*)d_in[8];
    const float* kb      = (const float*)d_in[10];
    const float* vb      = (const float*)d_in[12];
    const float* crossb  = (const float*)d_in[14];
    const float* crossrb = (const float*)d_in[16];
    const float* gateb   = (const float*)d_in[18];
    const float* bridgeb = (const float*)d_in[20];

    WSrc ws;
    ws.p[0] = (const float*)d_in[7];
    ws.p[1] = (const float*)d_in[9];
    ws.p[2] = (const float*)d_in[11];
    ws.p[3] = (const float*)d_in[13];
    ws.p[4] = (const float*)d_in[15];
    ws.p[5] = (const float*)d_in[19];
    ws.p[6] = (const float*)d_in[17];
    float* out = (float*)d_out;

    // smem for merged attention = size needed by largest (KT=192) variant
    auto smem_of = [](int KT) {
        int KH = KT / 2;
        int PST = KT * 2 + 16;
        int VW0 = KT / 16 + 1;
        int VST = 16 * (VW0 + ((VW0 & 1) ? 0 : 1));
        int kreg = (KH * 528 > 256 * VST) ? KH * 528 : 256 * VST;
        return 64 * 528 + kreg + 64 * PST + 256;
    };
    const int smem_attn = smem_of(192);
    cudaFuncSetAttribute(attn_all, cudaFuncAttributeMaxDynamicSharedMemorySize, smem_attn);

    conv_bands<<<dim3(SLAB / 1024, 1, 7), 256>>>(bp);
    conv_weights<<<dim3(917504 / 1024, 1, 7), 256>>>(ws);

    qkv_gemm<<<dim3(M_ROWS / 128, 2, 21), 256>>>(qb, kb, vb);

    attn_all<<<dim3(16, 8, 7), 256, smem_attn>>>();

    other_kernel<<<SLAB / 1024, 256>>>();
    u_gemm<<<dim3(M_ROWS / 128, 2, 7), 256>>>(crossb, crossrb, bridgeb);
    gate_gemm<<<dim3(M_ROWS / 128, 2, 7), 256>>>(bp, gateb, out);
}

// round 17
// speedup vs baseline: 1.0838x; 1.0390x over previous
#include <cuda_runtime.h>
#include <cuda_bf16.h>
#include <math.h>
#include <stdint.h>

// ---------------------------------------------------------------------------
// TemporalWormhole: bf16 m16n8k16 mma.sync GEMMs (R9/R13 core) + single-launch
// MMA flash attention (per-band KT, split-half K/V smem, natural-layout V via
// ldmatrix.trans, 2 CTAs/SM). B=8, T=1024, D=256. M = 8192 tokens/band.
// ---------------------------------------------------------------------------

#define D_DIM   256
#define M_ROWS  8192
#define SLAB    (M_ROWS * D_DIM)

__device__ float g_u[7 * SLAB];

__device__ __nv_bfloat16 g_qbf[7 * SLAB];
__device__ __nv_bfloat16 g_kbf[7 * SLAB];
__device__ __nv_bfloat16 g_vbf[7 * SLAB];
__device__ __nv_bfloat16 g_band_bf[7 * SLAB];
__device__ __nv_bfloat16 g_ctx_bf[7 * SLAB];
__device__ __nv_bfloat16 g_u_bf[7 * SLAB];
__device__ __nv_bfloat16 g_other_bf[SLAB];

#define OFF_QW  0
#define OFF_KW  458752
#define OFF_VW  917504
#define OFF_CW  1376256
#define OFF_CRW 1572864
#define OFF_BW  1769472
#define OFF_GW  1835008
__device__ __nv_bfloat16 g_wbf[2752512];

__constant__ int c_win[7] = {128, 64, 32, 16, 16, 8, 4};

struct BandPtrs { const float* p[7]; };
struct WSrc     { const float* p[7]; };

// ---------------------------- PTX helpers -----------------------------------
__device__ __forceinline__ uint32_t smem_u32(const void* p) {
    uint32_t a;
    asm("{ .reg .u64 t; cvta.to.shared.u64 t, %1; cvt.u32.u64 %0, t; }"
        : "=r"(a) : "l"(p));
    return a;
}

__device__ __forceinline__ void cp16(uint32_t dst, const void* src) {
    asm volatile("cp.async.cg.shared.global [%0], [%1], 16;"
                 :: "r"(dst), "l"(src) : "memory");
}
#define CP_COMMIT() asm volatile("cp.async.commit_group;" ::: "memory")
template<int N>
__device__ __forceinline__ void cp_wait() {
    asm volatile("cp.async.wait_group %0;" :: "n"(N) : "memory");
}

__device__ __forceinline__ void ldsm_x4(uint32_t addr, uint32_t r[4]) {
    asm volatile("ldmatrix.sync.aligned.m8n8.x4.shared.b16 {%0,%1,%2,%3}, [%4];"
        : "=r"(r[0]), "=r"(r[1]), "=r"(r[2]), "=r"(r[3]) : "r"(addr));
}

__device__ __forceinline__ void ldsm_x4_t(uint32_t addr, uint32_t r[4]) {
    asm volatile("ldmatrix.sync.aligned.m8n8.x4.trans.shared.b16 {%0,%1,%2,%3}, [%4];"
        : "=r"(r[0]), "=r"(r[1]), "=r"(r[2]), "=r"(r[3]) : "r"(addr));
}

__device__ __forceinline__ void mma_bf16(float4& d, const uint32_t a[4],
                                         uint32_t b0, uint32_t b1) {
    asm volatile(
        "mma.sync.aligned.m16n8k16.row.col.f32.bf16.bf16.f32 "
        "{%0,%1,%2,%3}, {%4,%5,%6,%7}, {%8,%9}, {%0,%1,%2,%3};"
        : "+f"(d.x), "+f"(d.y), "+f"(d.z), "+f"(d.w)
        : "r"(a[0]), "r"(a[1]), "r"(a[2]), "r"(a[3]), "r"(b0), "r"(b1));
}

// ---------------------------------------------------------------------------
// bf16 GEMM (exact R9/R13 core).
// ---------------------------------------------------------------------------

#define STAGES 4
#define ROWB   80

template<bool GATE>
__device__ __forceinline__ void issue_chunk(
    int kn, int tid, uint32_t sA, uint32_t sB,
    const __nv_bfloat16* __restrict__ A0, const __nv_bfloat16* __restrict__ A1,
    const __nv_bfloat16* __restrict__ W, int ldw, int row0, int col0)
{
    const __nv_bfloat16* Ab; int k0;
    if (GATE && kn >= 8) { Ab = A1; k0 = (kn - 8) * 32; }
    else                 { Ab = A0; k0 = kn * 32; }
    const int kw0 = kn * 32;
    const int s   = kn & (STAGES - 1);
#pragma unroll
    for (int i = 0; i < 2; i++) {
        int idx = tid + i * 256;
        int r = idx >> 2, q = idx & 3;
        uint32_t off = (uint32_t)((s * 128 + r) * ROWB + q * 16);
        cp16(sA + off, Ab + (size_t)(row0 + r) * 256 + k0 + q * 8);
        cp16(sB + off, W + (size_t)(col0 + r) * ldw + kw0 + q * 8);
    }
    CP_COMMIT();
}

template<int MODE>
__device__ __forceinline__ void gemm_body(
    const __nv_bfloat16* __restrict__ A0,
    const __nv_bfloat16* __restrict__ A1,
    const __nv_bfloat16* __restrict__ W, int ldw,
    const float* __restrict__ bias,
    float* __restrict__ C,
    __nv_bfloat16* __restrict__ Cbf,
    const float* __restrict__ Xf,
    const float* __restrict__ Uf)
{
    const bool GATE = (MODE == 2);
    const int NKT = GATE ? 16 : 8;
    __shared__ __align__(16) __nv_bfloat16 smA[STAGES * 128 * 40];
    __shared__ __align__(16) __nv_bfloat16 smB[STAGES * 128 * 40];

    const int tid  = threadIdx.x;
    const int wid  = tid >> 5;
    const int lane = tid & 31;
    const int g    = lane >> 2;
    const int t    = lane & 3;
    const int m0   = (wid & 1) * 64;
    const int n0   = (wid >> 1) * 32;
    const int row0 = blockIdx.x * 128;
    const int col0 = blockIdx.y * 128;
    const int lr   = lane & 15;
    const int lh   = lane >> 4;

    const uint32_t sA = smem_u32(smA);
    const uint32_t sB = smem_u32(smB);

    float4 acc[4][4];
#pragma unroll
    for (int mt = 0; mt < 4; mt++)
#pragma unroll
        for (int nt = 0; nt < 4; nt++) acc[mt][nt] = make_float4(0.f, 0.f, 0.f, 0.f);

    issue_chunk<GATE>(0, tid, sA, sB, A0, A1, W, ldw, row0, col0);
    issue_chunk<GATE>(1, tid, sA, sB, A0, A1, W, ldw, row0, col0);
    issue_chunk<GATE>(2, tid, sA, sB, A0, A1, W, ldw, row0, col0);

    for (int kt = 0; kt < NKT; kt++) {
        cp_wait<2>();
        __syncthreads();

        if (kt + 3 < NKT)
            issue_chunk<GATE>(kt + 3, tid, sA, sB, A0, A1, W, ldw, row0, col0);
        else
            CP_COMMIT();

        const int s = kt & (STAGES - 1);
        const uint32_t soff = (uint32_t)(s * 128 * ROWB);

#pragma unroll
        for (int kc = 0; kc < 2; kc++) {
            const uint32_t lbyte = (uint32_t)(lr * ROWB + kc * 32 + lh * 16);
            uint32_t af[4][4];
#pragma unroll
            for (int mt = 0; mt < 4; mt++)
                ldsm_x4(sA + soff + (uint32_t)((m0 + mt * 16) * ROWB) + lbyte, af[mt]);
            uint32_t bf[2][4];
#pragma unroll
            for (int nb = 0; nb < 2; nb++)
                ldsm_x4(sB + soff + (uint32_t)((n0 + nb * 16) * ROWB) + lbyte, bf[nb]);
#pragma unroll
            for (int mt = 0; mt < 4; mt++)
#pragma unroll
                for (int nt = 0; nt < 4; nt++)
                    mma_bf16(acc[mt][nt], af[mt],
                             bf[nt >> 1][nt & 1], bf[nt >> 1][(nt & 1) + 2]);
        }
    }

#pragma unroll
    for (int nt = 0; nt < 4; nt++) {
        int col = col0 + n0 + nt * 8 + 2 * t;
        float bx = bias[col], by = bias[col + 1];
#pragma unroll
        for (int mt = 0; mt < 4; mt++) {
            int r0 = row0 + m0 + mt * 16 + g;
            int r1 = r0 + 8;
            float4 a = acc[mt][nt];
            float v0x = a.x + bx, v0y = a.y + by;
            float v1x = a.z + bx, v1y = a.w + by;
            size_t o0 = (size_t)r0 * 256 + col;
            size_t o1 = (size_t)r1 * 256 + col;
            if (MODE == 0) {
                *(float2*)&C[o0] = make_float2(v0x, v0y);
                *(float2*)&C[o1] = make_float2(v1x, v1y);
            } else if (MODE == 1) {
                *(float2*)&C[o0] = make_float2(v0x, v0y);
                *(float2*)&C[o1] = make_float2(v1x, v1y);
                *(__nv_bfloat162*)&Cbf[o0] = __floats2bfloat162_rn(v0x, v0y);
                *(__nv_bfloat162*)&Cbf[o1] = __floats2bfloat162_rn(v1x, v1y);
            } else if (MODE == 3) {
                *(__nv_bfloat162*)&Cbf[o0] = __floats2bfloat162_rn(v0x, v0y);
                *(__nv_bfloat162*)&Cbf[o1] = __floats2bfloat162_rn(v1x, v1y);
            } else {
                float2 x0 = *(const float2*)&Xf[o0];
                float2 x1 = *(const float2*)&Xf[o1];
                float2 u0 = *(const float2*)&Uf[o0];
                float2 u1 = *(const float2*)&Uf[o1];
                float2 w0, w1;
                w0.x = x0.x + u0.x / (1.f + __expf(-v0x));
                w0.y = x0.y + u0.y / (1.f + __expf(-v0y));
                w1.x = x1.x + u1.x / (1.f + __expf(-v1x));
                w1.y = x1.y + u1.y / (1.f + __expf(-v1y));
                *(float2*)&C[o0] = w0;
                *(float2*)&C[o1] = w1;
            }
        }
    }
}

// ---------------- conversion kernels -----------------------------------------
__global__ void conv_bands(BandPtrs bp)
{
    int z = blockIdx.z;
    int i4 = (blockIdx.x * blockDim.x + threadIdx.x) * 4;
    if (i4 >= SLAB) return;
    float4 v = *(const float4*)&bp.p[z][i4];
    __nv_bfloat16* d = g_band_bf + (size_t)z * SLAB + i4;
    *(__nv_bfloat162*)&d[0] = __floats2bfloat162_rn(v.x, v.y);
    *(__nv_bfloat162*)&d[2] = __floats2bfloat162_rn(v.z, v.w);
}

__global__ void conv_weights(WSrc ws)
{
    const int sizes[7] = {458752, 458752, 458752, 196608, 196608, 65536, 917504};
    const int offs[7]  = {OFF_QW, OFF_KW, OFF_VW, OFF_CW, OFF_CRW, OFF_BW, OFF_GW};
    int z = blockIdx.z;
    int i4 = (blockIdx.x * blockDim.x + threadIdx.x) * 4;
    if (i4 >= sizes[z]) return;
    float4 v = *(const float4*)&ws.p[z][i4];
    __nv_bfloat16* d = g_wbf + offs[z] + i4;
    *(__nv_bfloat162*)&d[0] = __floats2bfloat162_rn(v.x, v.y);
    *(__nv_bfloat162*)&d[2] = __floats2bfloat162_rn(v.z, v.w);
}

// ---------------- K1: QKV projections -> bf16 --------------------------------
__global__ void __launch_bounds__(256)
qkv_gemm(const float* __restrict__ qb, const float* __restrict__ kb,
         const float* __restrict__ vb)
{
    int z = blockIdx.z;
    int n = z / 3, which = z - 3 * n;
    const __nv_bfloat16* A = g_band_bf + (size_t)n * SLAB;
    const __nv_bfloat16* W; const float* bias; __nv_bfloat16* C;
    if (which == 0)      { W = g_wbf + OFF_QW + (size_t)n * 65536; bias = qb + n * 256; C = g_qbf + (size_t)n * SLAB; }
    else if (which == 1) { W = g_wbf + OFF_KW + (size_t)n * 65536; bias = kb + n * 256; C = g_kbf + (size_t)n * SLAB; }
    else                 { W = g_wbf + OFF_VW + (size_t)n * 65536; bias = vb + n * 256; C = g_vbf + (size_t)n * SLAB; }
    gemm_body<3>(A, nullptr, W, 256, bias, nullptr, C, nullptr, nullptr);
}

// ---------------------------------------------------------------------------
// K2: attention body. Split-half K/V smem; V kept in NATURAL [key][dim]
// layout (same loads as K) and consumed via ldmatrix.trans. Fragment pairing
// for trans: n-group0 = (r0, r1), n-group1 = (r2, r3). Math identical to R16.
// ---------------------------------------------------------------------------

template<int KT>
__device__ __forceinline__ void attn_body(int n, int b, int t0)
{
    static_assert((KT / 2) % 16 == 0, "KH must be a multiple of 16");
    constexpr int KH   = KT / 2;
    constexpr int KB0  = KT - 64;
    constexpr int QST  = 528;
    constexpr int PST  = KT * 2 + 16;
    constexpr int KREG = KH * QST;       // K/V half region (same layout)
    constexpr int OFFQ = 0;
    constexpr int OFFK = 64 * QST;
    constexpr int OFFP = OFFK + KREG;
    constexpr int OFFR = OFFP + 64 * PST;

    extern __shared__ char sm[];
    const uint32_t s32 = smem_u32(sm);
    float* rsum = (float*)(sm + OFFR);

    const int w  = c_win[n];
    const int kb0 = t0 - KB0;
    const size_t slab = ((size_t)n * M_ROWS + (size_t)b * 1024) * 256;

    const int tid = threadIdx.x, wid = tid >> 5, lane = tid & 31;
    const int g = lane >> 2, t = lane & 3, lr = lane & 15, lh = lane >> 4;

    // ---- load Q once ----
    {
        const __nv_bfloat16* Qg = g_qbf + slab + (size_t)t0 * 256;
#pragma unroll
        for (int i = 0; i < 8; i++) {
            int idx = tid + i * 256; int r = idx >> 5, c = idx & 31;
            cp16(s32 + OFFQ + r * QST + c * 16, Qg + (size_t)r * 256 + c * 8);
        }
    }

    float4 sacc[KT / 8];
#pragma unroll
    for (int i = 0; i < KT / 8; i++) sacc[i] = make_float4(0.f, 0.f, 0.f, 0.f);

    // ---- phase 1: scores, two K halves ----
#pragma unroll
    for (int h = 0; h < 2; h++) {
        const __nv_bfloat16* Kg = g_kbf + slab;
#pragma unroll
        for (int i = 0; i < KH / 8; i++) {
            int idx = tid + i * 256; int r = idx >> 5, c = idx & 31;
            int jr = kb0 + h * KH + r; jr = jr < 0 ? 0 : jr;
            cp16(s32 + OFFK + r * QST + c * 16, Kg + (size_t)jr * 256 + c * 8);
        }
        CP_COMMIT();
        cp_wait<0>();
        __syncthreads();

        if (wid < 4) {
            const int m0 = wid * 16;
#pragma unroll
            for (int kc = 0; kc < 16; kc++) {
                uint32_t af[4];
                ldsm_x4(s32 + OFFQ + (m0 + lr) * QST + kc * 32 + lh * 16, af);
#pragma unroll
                for (int nb = 0; nb < KH / 16; nb++) {
                    uint32_t bf[4];
                    ldsm_x4(s32 + OFFK + (nb * 16 + lr) * QST + kc * 32 + lh * 16, bf);
                    mma_bf16(sacc[h * (KH / 8) + 2 * nb],     af, bf[0], bf[2]);
                    mma_bf16(sacc[h * (KH / 8) + 2 * nb + 1], af, bf[1], bf[3]);
                }
            }
        }
        __syncthreads();
    }

    // ---- prefetch V half 0 (natural layout) into K region; overlaps softmax
    {
        const __nv_bfloat16* Vg = g_vbf + slab;
#pragma unroll
        for (int i = 0; i < KH / 8; i++) {
            int idx = tid + i * 256; int r = idx >> 5, c = idx & 31;
            int jr = kb0 + r; jr = jr < 0 ? 0 : jr;
            cp16(s32 + OFFK + r * QST + c * 16, Vg + (size_t)jr * 256 + c * 8);
        }
        CP_COMMIT();
    }

    // ---- phase 2: masked softmax ----
    if (wid < 4) {
        const int m0 = wid * 16;
        const int tq0 = t0 + m0 + g, tq1 = tq0 + 8;
        const int lo0 = max(0, tq0 - w + 1), lo1 = max(0, tq1 - w + 1);
        const float scale = 0.0625f;
        float mx0 = -1e30f, mx1 = -1e30f;
#pragma unroll
        for (int nt = 0; nt < KT / 8; nt++) {
            int jg = kb0 + nt * 8 + 2 * t;
            float4 s = sacc[nt];
            s.x = (jg     >= lo0 && jg     <= tq0) ? s.x * scale : -1e30f;
            s.y = (jg + 1 >= lo0 && jg + 1 <= tq0) ? s.y * scale : -1e30f;
            s.z = (jg     >= lo1 && jg     <= tq1) ? s.z * scale : -1e30f;
            s.w = (jg + 1 >= lo1 && jg + 1 <= tq1) ? s.w * scale : -1e30f;
            sacc[nt] = s;
            mx0 = fmaxf(mx0, fmaxf(s.x, s.y));
            mx1 = fmaxf(mx1, fmaxf(s.z, s.w));
        }
        mx0 = fmaxf(mx0, __shfl_xor_sync(0xffffffffu, mx0, 1));
        mx0 = fmaxf(mx0, __shfl_xor_sync(0xffffffffu, mx0, 2));
        mx1 = fmaxf(mx1, __shfl_xor_sync(0xffffffffu, mx1, 1));
        mx1 = fmaxf(mx1, __shfl_xor_sync(0xffffffffu, mx1, 2));

        float sum0 = 0.f, sum1 = 0.f;
#pragma unroll
        for (int nt = 0; nt < KT / 8; nt++) {
            float4 s = sacc[nt];
            float e0 = __expf(s.x - mx0), e1 = __expf(s.y - mx0);
            float e2 = __expf(s.z - mx1), e3 = __expf(s.w - mx1);
            sum0 += e0 + e1; sum1 += e2 + e3;
            char* p0 = sm + OFFP + (m0 + g) * PST + (nt * 8 + 2 * t) * 2;
            *(__nv_bfloat162*)p0             = __floats2bfloat162_rn(e0, e1);
            *(__nv_bfloat162*)(p0 + 8 * PST) = __floats2bfloat162_rn(e2, e3);
        }
        sum0 += __shfl_xor_sync(0xffffffffu, sum0, 1);
        sum0 += __shfl_xor_sync(0xffffffffu, sum0, 2);
        sum1 += __shfl_xor_sync(0xffffffffu, sum1, 1);
        sum1 += __shfl_xor_sync(0xffffffffu, sum1, 2);
        if (t == 0) {
            rsum[m0 + g]     = 1.f / sum0;
            rsum[m0 + g + 8] = 1.f / sum1;
        }
    }

    // ---- phase 3: O = P @ V (natural V + ldsm.trans), two halves ----
    const int m0o = (wid & 3) * 16;
    const int n0o = (wid >> 2) * 128;
    float4 oacc[16];
#pragma unroll
    for (int i = 0; i < 16; i++) oacc[i] = make_float4(0.f, 0.f, 0.f, 0.f);

#pragma unroll
    for (int h = 0; h < 2; h++) {
        if (h == 1) {
            // load V half 1 (after all readers of half 0 are done)
            const __nv_bfloat16* Vg = g_vbf + slab;
#pragma unroll
            for (int i = 0; i < KH / 8; i++) {
                int idx = tid + i * 256; int r = idx >> 5, c = idx & 31;
                int jr = kb0 + KH + r;
                jr = jr < 0 ? 0 : (jr > 1023 ? 1023 : jr);
                cp16(s32 + OFFK + r * QST + c * 16, Vg + (size_t)jr * 256 + c * 8);
            }
            CP_COMMIT();
        }
        cp_wait<0>();
        __syncthreads();

#pragma unroll
        for (int kc = 0; kc < KH / 16; kc++) {
            uint32_t af[4];
            ldsm_x4(s32 + OFFP + (m0o + lr) * PST + h * KH * 2 + kc * 32 + lh * 16, af);
#pragma unroll
            for (int nb = 0; nb < 8; nb++) {
                uint32_t bf[4];
                // rows = key (kc*16 + lr), cols = dim (n0o + nb*16), trans load
                ldsm_x4_t(s32 + OFFK + (kc * 16 + lr) * QST
                          + (uint32_t)(n0o + nb * 16) * 2 + lh * 16, bf);
                mma_bf16(oacc[2 * nb],     af, bf[0], bf[1]);
                mma_bf16(oacc[2 * nb + 1], af, bf[2], bf[3]);
            }
        }
        __syncthreads();
    }

    {
        const float i0 = rsum[m0o + g], i1 = rsum[m0o + g + 8];
        __nv_bfloat16* Cg = g_ctx_bf + slab + (size_t)(t0 + m0o + g) * 256;
#pragma unroll
        for (int nt = 0; nt < 16; nt++) {
            int col = n0o + nt * 8 + 2 * t;
            float4 o = oacc[nt];
            *(__nv_bfloat162*)&Cg[col]           = __floats2bfloat162_rn(o.x * i0, o.y * i0);
            *(__nv_bfloat162*)&Cg[8 * 256 + col] = __floats2bfloat162_rn(o.z * i1, o.w * i1);
        }
    }
}

// Single-launch attention: grid (16, 8, 7); per-band KT dispatch.
__global__ void __launch_bounds__(256, 2)
attn_all()
{
    const int n  = blockIdx.z;
    const int b  = blockIdx.y;
    const int t0 = blockIdx.x * 64;
    if (n == 0)      attn_body<192>(n, b, t0);
    else if (n == 1) attn_body<128>(n, b, t0);
    else             attn_body<96>(n, b, t0);
}

// ---------------- K3: other = mean of ctx over bands != 3 -------------------
__global__ void other_kernel()
{
    int i4 = (blockIdx.x * blockDim.x + threadIdx.x) * 4;
    if (i4 >= SLAB) return;
    float4 s = {0.f, 0.f, 0.f, 0.f};
#pragma unroll
    for (int nn = 0; nn < 7; nn++) {
        if (nn == 3) continue;
        const __nv_bfloat162* p = (const __nv_bfloat162*)&g_ctx_bf[(size_t)nn * SLAB + i4];
        float2 a = __bfloat1622float2(p[0]);
        float2 b = __bfloat1622float2(p[1]);
        s.x += a.x; s.y += a.y; s.z += b.x; s.w += b.y;
    }
    const float k = 1.f / 6.f;
    __nv_bfloat16* d = g_other_bf + i4;
    *(__nv_bfloat162*)&d[0] = __floats2bfloat162_rn(s.x * k, s.y * k);
    *(__nv_bfloat162*)&d[2] = __floats2bfloat162_rn(s.z * k, s.w * k);
}

// ---------------- K4: per-band update projections u[n] (fp32 + bf16) --------
__global__ void __launch_bounds__(256)
u_gemm(const float* __restrict__ crossb, const float* __restrict__ crossrb,
       const float* __restrict__ bridgeb)
{
    int n = blockIdx.z;
    const __nv_bfloat16 *A, *W; const float* bias;
    switch (n) {
        case 0:  A = g_ctx_bf + (size_t)6 * SLAB; W = g_wbf + OFF_CRW;             bias = crossrb;       break;
        case 1:  A = g_ctx_bf + (size_t)5 * SLAB; W = g_wbf + OFF_CRW + 65536;     bias = crossrb + 256; break;
        case 2:  A = g_ctx_bf + (size_t)4 * SLAB; W = g_wbf + OFF_CRW + 2 * 65536; bias = crossrb + 512; break;
        case 3:  A = g_other_bf;                  W = g_wbf + OFF_BW;              bias = bridgeb;       break;
        case 4:  A = g_ctx_bf + (size_t)2 * SLAB; W = g_wbf + OFF_CW + 2 * 65536;  bias = crossb + 512;  break;
        case 5:  A = g_ctx_bf + (size_t)1 * SLAB; W = g_wbf + OFF_CW + 65536;      bias = crossb + 256;  break;
        default: A = g_ctx_bf;                    W = g_wbf + OFF_CW;              bias = crossb;        break;
    }
    gemm_body<1>(A, nullptr, W, 256, bias,
                 g_u + (size_t)n * SLAB, g_u_bf + (size_t)n * SLAB, nullptr, nullptr);
}

// ---------------- K5: gate GEMM (K=512) + sigmoid + residual ----------------
__global__ void __launch_bounds__(256)
gate_gemm(BandPtrs bp, const float* __restrict__ gateb, float* __restrict__ out)
{
    int n = blockIdx.z;
    gemm_body<2>(g_band_bf + (size_t)n * SLAB, g_u_bf + (size_t)n * SLAB,
                 g_wbf + OFF_GW + (size_t)n * 131072, 512,
                 gateb + n * 256,
                 out + (size_t)n * SLAB, nullptr,
                 bp.p[n], g_u + (size_t)n * SLAB);
}

// ---------------------------------------------------------------------------
extern "C" void kernel_launch(void* const* d_in, const int* in_sizes, int n_in,
                              void* d_out, int out_size)
{
    BandPtrs bp;
    for (int i = 0; i < 7; i++) bp.p[i] = (const float*)d_in[i];
    const float* qb      = (const float*)d_in[8];
    const float* kb      = (const float*)d_in[10];
    const float* vb      = (const float*)d_in[12];
    const float* crossb  = (const float*)d_in[14];
    const float* crossrb = (const float*)d_in[16];
    const float* gateb   = (const float*)d_in[18];
    const float* bridgeb = (const float*)d_in[20];

    WSrc ws;
    ws.p[0] = (const float*)d_in[7];
    ws.p[1] = (const float*)d_in[9];
    ws.p[2] = (const float*)d_in[11];
    ws.p[3] = (const float*)d_in[13];
    ws.p[4] = (const float*)d_in[15];
    ws.p[5] = (const float*)d_in[19];
    ws.p[6] = (const float*)d_in[17];
    float* out = (float*)d_out;

    // smem = largest (KT=192) variant: Q + K/V half + P + rsum
    auto smem_of = [](int KT) {
        int KH = KT / 2;
        int PST = KT * 2 + 16;
        return 64 * 528 + KH * 528 + 64 * PST + 256;
    };
    const int smem_attn = smem_of(192);
    cudaFuncSetAttribute(attn_all, cudaFuncAttributeMaxDynamicSharedMemorySize, smem_attn);

    conv_bands<<<dim3(SLAB / 1024, 1, 7), 256>>>(bp);
    conv_weights<<<dim3(917504 / 1024, 1, 7), 256>>>(ws);

    qkv_gemm<<<dim3(M_ROWS / 128, 2, 21), 256>>>(qb, kb, vb);

    attn_all<<<dim3(16, 8, 7), 256, smem_attn>>>();

    other_kernel<<<SLAB / 1024, 256>>>();
    u_gemm<<<dim3(M_ROWS / 128, 2, 7), 256>>>(crossb, crossrb, bridgeb);
    gate_gemm<<<dim3(M_ROWS / 128, 2, 7), 256>>>(bp, gateb, out);
}